// round 15
// baseline (speedup 1.0000x reference)
#include <cuda_runtime.h>
#include <math.h>

#define NN 100000
#define NE 1600000
#define ESL (NE + NN)
#define NGRAPH 64
#define NEG 0.2f
#define SCB 196          // scan blocks (ceil(NN/512))
#define CSB 592          // countscan blocks: 4/SM x 148 -> co-residency guaranteed
#define PB  1184         // project blocks inside fused fill2+proj kernel

// ---------------- scratch (device globals; no allocation) ----------------
__device__ float    d_cnt[NN];
__device__ float    d_mean[NN * 8];
__device__ float    d_xp[NN * 64];
__device__ float    d_als[NN * 4];
__device__ float    d_ald[NN * 4];
__device__ float    d_h0[NN * 64];
__device__ float    d_h1[NN * 64];
__device__ float    d_pool[NGRAPH * 64];
__device__ float    d_gcnt[NGRAPH];
__device__ float    d_weatt[3 * 32];
// CSR
__device__ int      d_roff[NN + 1];
__device__ int      d_cur[NN];
__device__ int      d_eid[ESL];                 // CSR slot -> original edge id
__device__ int      d_csrc[ESL];                // CSR slot -> src node (coalesced write)
__device__ float    d_ale[3][(size_t)ESL * 4];  // per-layer edge logits (coalesced write)
__device__ int      d_flagsum[SCB];             // lookback: 0 = not ready, else localsum+1
__device__ int      d_done;                     // countscan global-barrier counter

// ---------------- helpers ----------------
__device__ __forceinline__ void red2(float* p, float a, float b) {
    asm volatile("red.global.add.v2.f32 [%0], {%1, %2};" :: "l"(p), "f"(a), "f"(b) : "memory");
}

// ---------------- fused: count (+weatt) -> global barrier -> lookback scan ----------------
__global__ void __launch_bounds__(256)
k_countscan(const int* __restrict__ dst, const float* __restrict__ ea,
            const float* __restrict__ We0, const float* __restrict__ ae0,
            const float* __restrict__ Weh, const float* __restrict__ aeh) {
    __shared__ int sh[256];
    __shared__ int sp[256];
    int t = threadIdx.x, bid = blockIdx.x;
    int gt = bid * 256 + t;

    // ---- phase 1: in-degree count + self-loop mean sums (grid-stride) ----
    for (int e = gt; e < NE; e += CSB * 256) {
        int dd = dst[e];
        atomicAdd(&d_cnt[dd], 1.0f);
#pragma unroll
        for (int d = 0; d < 8; d += 2)
            red2(&d_mean[dd * 8 + d], ea[(size_t)e * 8 + d], ea[(size_t)e * 8 + d + 1]);
    }
    if (gt < 96) {
        int l = gt >> 5, r = gt & 31;
        int d = r >> 2, h = r & 3;
        const float* We = (l == 0) ? We0 : (Weh + (l - 1) * 512);
        const float* ae = (l == 0) ? ae0 : (aeh + (l - 1) * 64);
        float s = 0.0f;
#pragma unroll
        for (int c = 0; c < 16; c++) s += We[d * 64 + h * 16 + c] * ae[h * 16 + c];
        d_weatt[l * 32 + d * 4 + h] = s;
    }
    if (gt == 0) d_roff[NN] = ESL;

    // ---- global barrier (all CSB blocks co-resident by construction) ----
    __threadfence();
    __syncthreads();
    if (t == 0) {
        atomicAdd(&d_done, 1);
        while (atomicAdd(&d_done, 0) < CSB) { }
    }
    __syncthreads();

    // ---- phase 2: exclusive scan of degrees (blocks 0..SCB-1) ----
    if (bid >= SCB) return;
    int nb = bid * 512 + t * 2;
    int d0 = 0, d1 = 0;
    if (nb < NN) {                      // NN even -> nb+1 < NN too
        float2 c = __ldcg((const float2*)&d_cnt[nb]);   // L2 read (skip stale L1)
        d0 = (int)(c.x + 0.5f) + 1;
        d1 = (int)(c.y + 0.5f) + 1;
    }
    sh[t] = d0 + d1;
    __syncthreads();
#pragma unroll
    for (int off = 1; off < 256; off <<= 1) {
        int v = (t >= off) ? sh[t - off] : 0;
        __syncthreads();
        sh[t] += v;
        __syncthreads();
    }
    int total = sh[255];
    if (t == 0) {
        __threadfence();
        atomicExch(&d_flagsum[bid], total + 1);
    }
    int pre = 0;
    if (t < bid) {
        volatile int* f = &d_flagsum[t];
        int x;
        while ((x = *f) == 0) { }
        pre = x - 1;
    }
    sp[t] = pre;
    __syncthreads();
#pragma unroll
    for (int off = 128; off; off >>= 1) {
        if (t < off) sp[t] += sp[t + off];
        __syncthreads();
    }
    int base = sp[0];
    int off0 = base + sh[t] - (d0 + d1);
    if (nb < NN) {
        d_roff[nb] = off0;          d_cur[nb] = off0;
        d_roff[nb + 1] = off0 + d0; d_cur[nb + 1] = off0 + d0;
    }
}

// ---------------- fill pass 1: permutation only (one 4B scattered store per edge) ----------------
__global__ void k_fill1(const int* __restrict__ dst) {
    int e = blockIdx.x * blockDim.x + threadIdx.x;
    if (e >= ESL) return;
    int dd = (e < NE) ? dst[e] : e - NE;
    int pos = atomicAdd(&d_cur[dd], 1);
    d_eid[pos] = e;
}

// ---------------- projection body: warp handles 4 nodes x 64 cols (2 cols/lane).
// w-loads amortized across 4 nodes: 4x less smem traffic per FMA.
__device__ __forceinline__ void project_body(
        int bid, int nblocks,
        const float* __restrict__ X, int fin, const float* __restrict__ W,
        const float* __restrict__ as_, const float* __restrict__ ad_,
        float* sW, float* sx, float* sa, float* sd) {
    int tid = threadIdx.x;
    for (int i = tid; i < fin * 64; i += 256) sW[i] = W[i];
    if (tid < 64) { sa[tid] = as_[tid]; sd[tid] = ad_[tid]; }
    __syncthreads();
    int wid = tid >> 5;                 // warp handles nodes [wid*4, wid*4+4)
    int lane = tid & 31;
    int c2 = lane * 2;                  // this lane's two output cols
    int lf = (fin == 64) ? 6 : 5;
    int fmask = fin - 1;
    for (int base = bid * 32; base < NN; base += nblocks * 32) {
        for (int i = tid; i < 32 * fin; i += 256) {
            int nl = i >> lf, c = i & fmask;
            sx[nl * 64 + c] = X[(size_t)(base + nl) * fin + c];
        }
        __syncthreads();
        int n0 = base + wid * 4;
        const float* xr = sx + (size_t)(wid * 4) * 64;
        float acc[4][2] = {{0,0},{0,0},{0,0},{0,0}};
#pragma unroll 2
        for (int i = 0; i < fin; i += 4) {
            float4 x0 = *(const float4*)(xr + 0 * 64 + i);   // broadcast: 1 phase
            float4 x1 = *(const float4*)(xr + 1 * 64 + i);
            float4 x2 = *(const float4*)(xr + 2 * 64 + i);
            float4 x3 = *(const float4*)(xr + 3 * 64 + i);
            float2 w0 = *(const float2*)(sW + (i + 0) * 64 + c2);
            float2 w1 = *(const float2*)(sW + (i + 1) * 64 + c2);
            float2 w2 = *(const float2*)(sW + (i + 2) * 64 + c2);
            float2 w3 = *(const float2*)(sW + (i + 3) * 64 + c2);
            acc[0][0] += x0.x*w0.x + x0.y*w1.x + x0.z*w2.x + x0.w*w3.x;
            acc[0][1] += x0.x*w0.y + x0.y*w1.y + x0.z*w2.y + x0.w*w3.y;
            acc[1][0] += x1.x*w0.x + x1.y*w1.x + x1.z*w2.x + x1.w*w3.x;
            acc[1][1] += x1.x*w0.y + x1.y*w1.y + x1.z*w2.y + x1.w*w3.y;
            acc[2][0] += x2.x*w0.x + x2.y*w1.x + x2.z*w2.x + x2.w*w3.x;
            acc[2][1] += x2.x*w0.y + x2.y*w1.y + x2.z*w2.y + x2.w*w3.y;
            acc[3][0] += x3.x*w0.x + x3.y*w1.x + x3.z*w2.x + x3.w*w3.x;
            acc[3][1] += x3.x*w0.y + x3.y*w1.y + x3.z*w2.y + x3.w*w3.y;
        }
#pragma unroll
        for (int nl = 0; nl < 4; nl++) {
            int n = n0 + nl;
            *(float2*)(d_xp + (size_t)n * 64 + c2) = make_float2(acc[nl][0], acc[nl][1]);
            float ps = acc[nl][0] * sa[c2] + acc[nl][1] * sa[c2 + 1];
            float pd = acc[nl][0] * sd[c2] + acc[nl][1] * sd[c2 + 1];
#pragma unroll
            for (int off = 4; off; off >>= 1) {
                ps += __shfl_xor_sync(0xffffffffu, ps, off);
                pd += __shfl_xor_sync(0xffffffffu, pd, off);
            }
            if ((lane & 7) == 0) {
                int h = lane >> 3;
                d_als[n * 4 + h] = ps;
                d_ald[n * 4 + h] = pd;
            }
        }
        __syncthreads();
    }
}

// ---------------- fill pass 2: thread = CSR slot; gather-compute, coalesced writes ----------------
__device__ __forceinline__ void fill2_body(int slot, const int* __restrict__ src,
                                           const float* __restrict__ ea, const float* sw) {
    int e = d_eid[slot];                 // coalesced
    int s;
    float a[8];
    if (e < NE) {
        s = src[e];                      // scattered 4B read (clean sector fetch)
        const float4* ap = (const float4*)(ea + (size_t)e * 8);  // scattered 32B read
        float4 v0 = ap[0], v1 = ap[1];
        a[0] = v0.x; a[1] = v0.y; a[2] = v0.z; a[3] = v0.w;
        a[4] = v1.x; a[5] = v1.y; a[6] = v1.z; a[7] = v1.w;
    } else {
        int n = e - NE;
        s = n;
        const float4* ap = (const float4*)(d_mean + (size_t)n * 8);
        float4 v0 = ap[0], v1 = ap[1];
        float ic = 1.0f / fmaxf(d_cnt[n], 1.0f);
        a[0] = v0.x * ic; a[1] = v0.y * ic; a[2] = v0.z * ic; a[3] = v0.w * ic;
        a[4] = v1.x * ic; a[5] = v1.y * ic; a[6] = v1.z * ic; a[7] = v1.w * ic;
    }
    d_csrc[slot] = s;                    // coalesced
#pragma unroll
    for (int l = 0; l < 3; l++) {
        float4 o;
        float* po = (float*)&o;
#pragma unroll
        for (int h = 0; h < 4; h++) {
            float sum = 0.0f;
#pragma unroll
            for (int d = 0; d < 8; d++) sum += a[d] * sw[l * 32 + d * 4 + h];
            po[h] = sum;
        }
        *(float4*)(&d_ale[l][(size_t)slot * 4]) = o;   // coalesced 16B
    }
}

// ---------------- fused: fill2 (blocks >= PB) + project layer0 (blocks < PB) ----------------
__global__ void k_fill2proj(const int* __restrict__ src, const float* __restrict__ ea,
                            const float* __restrict__ X, int fin, const float* __restrict__ W,
                            const float* __restrict__ as_, const float* __restrict__ ad_) {
    __shared__ float sW[64 * 64];
    __shared__ float sx[32 * 64];
    __shared__ float sa[64], sd[64];
    __shared__ float sw[96];
    if (blockIdx.x < PB) {
        project_body(blockIdx.x, PB, X, fin, W, as_, ad_, sW, sx, sa, sd);
        return;
    }
    if (threadIdx.x < 96) sw[threadIdx.x] = d_weatt[threadIdx.x];
    __syncthreads();
    int slot = (blockIdx.x - PB) * 256 + threadIdx.x;
    if (slot >= ESL) return;
    fill2_body(slot, src, ea, sw);
}

// ---------------- standalone projection (layers 1,2) ----------------
__global__ void k_project(const float* __restrict__ X, int fin, const float* __restrict__ W,
                          const float* __restrict__ as_, const float* __restrict__ ad_) {
    __shared__ float sW[64 * 64];
    __shared__ float sx[32 * 64];
    __shared__ float sa[64], sd[64];
    project_body(blockIdx.x, gridDim.x, X, fin, W, as_, ad_, sW, sx, sa, sd);
}

// ---------------- fused single-pass softmax-aggregate
// producer: lane = h*8+sub computes coef for (edge sub, head h), distance-1 pipelined.
// consumer: 2 xp rows per j-step; lane covers cols (lane&15)*4 of row-group lane>>4.
// epilogue: shfl-xor-16 combine; lanes 0-15 write float4.
__global__ void __launch_bounds__(64)
k_agg(const float* __restrict__ ale, const float* __restrict__ b,
      int dorelu, float* __restrict__ out,
      const int* __restrict__ batch, int dopool) {
    int tid = threadIdx.x;
    int warp = (blockIdx.x * 64 + tid) >> 5;
    if (warp >= NN) return;
    int lane = tid & 31;
    int h = lane >> 3, sub = lane & 7;   // producer role
    int r = lane >> 4;                   // consumer row-group (edge parity)
    int q = lane & 15;                   // consumer col quad: cols [q*4, q*4+4)
    int hq = q >> 2;                     // head of those cols
    int beg = d_roff[warp];
    int end = d_roff[warp + 1];
    float ald_h = d_ald[warp * 4 + h];

    // pipeline prologue
    int myp = beg + sub;
    int s = 0;
    float av = -INFINITY;                // invalid lanes: alpha = -inf -> exp = 0
    if (myp < end) {
        s = d_csrc[myp];
        av = ale[(size_t)myp * 4 + h];
    }
    float alsv = d_als[s * 4 + h];

    float den = 0.0f, a0 = 0.0f, a1 = 0.0f, a2 = 0.0f, a3 = 0.0f;
    for (int p0 = beg; p0 < end; p0 += 8) {
        float a = alsv + ald_h + av;
        float al = a > 0.0f ? a : NEG * a;
        float c = __expf(al);
        int scur = s;
        int myp2 = p0 + 8 + sub;
        s = 0; av = -INFINITY;
        if (myp2 < end) {
            s = d_csrc[myp2];
            av = ale[(size_t)myp2 * 4 + h];
        }
        alsv = d_als[s * 4 + h];
#pragma unroll
        for (int j = 0; j < 4; j++) {
            int eidx = 2 * j + r;
            float cj = __shfl_sync(0xffffffffu, c, hq * 8 + eidx);
            int   sj = __shfl_sync(0xffffffffu, scur, eidx);
            float4 v = *(const float4*)(d_xp + (size_t)sj * 64 + q * 4);
            den += cj; a0 += cj * v.x; a1 += cj * v.y; a2 += cj * v.z; a3 += cj * v.w;
        }
    }
    // combine the two row-groups (lanes L and L+16 cover identical cols)
    den += __shfl_xor_sync(0xffffffffu, den, 16);
    a0  += __shfl_xor_sync(0xffffffffu, a0, 16);
    a1  += __shfl_xor_sync(0xffffffffu, a1, 16);
    a2  += __shfl_xor_sync(0xffffffffu, a2, 16);
    a3  += __shfl_xor_sync(0xffffffffu, a3, 16);
    if (lane < 16) {
        float inv = 1.0f / (den + 1e-16f);
        float4 bb = *(const float4*)(b + q * 4);
        float o0 = a0 * inv + bb.x;
        float o1 = a1 * inv + bb.y;
        float o2 = a2 * inv + bb.z;
        float o3 = a3 * inv + bb.w;
        if (dorelu) {
            o0 = fmaxf(o0, 0.0f); o1 = fmaxf(o1, 0.0f);
            o2 = fmaxf(o2, 0.0f); o3 = fmaxf(o3, 0.0f);
        }
        if (dopool) {
            int g = batch[warp];
            red2(&d_pool[g * 64 + q * 4], o0, o1);
            red2(&d_pool[g * 64 + q * 4 + 2], o2, o3);
            if (q == 0) atomicAdd(&d_gcnt[g], 1.0f);
        } else {
            *(float4*)(out + (size_t)warp * 64 + q * 4) = make_float4(o0, o1, o2, o3);
        }
    }
}

// ---------------- MLP head ----------------
__global__ void k_mlp(const float* __restrict__ fc1w, const float* __restrict__ fc1b,
                      const float* __restrict__ fc2w, const float* __restrict__ fc2b,
                      float* __restrict__ out) {
    int g = threadIdx.x;
    if (g >= NGRAPH) return;
    float ic = 1.0f / fmaxf(d_gcnt[g], 1.0f);
    float hr[64];
#pragma unroll
    for (int c = 0; c < 64; c++) hr[c] = d_pool[g * 64 + c] * ic;
    float y1[32];
#pragma unroll
    for (int j = 0; j < 32; j++) {
        float s = fc1b[j];
#pragma unroll
        for (int c = 0; c < 64; c++) s += hr[c] * fc1w[c * 32 + j];
        y1[j] = fmaxf(s, 0.0f);
    }
#pragma unroll
    for (int o = 0; o < 2; o++) {
        float s = fc2b[o];
#pragma unroll
        for (int j = 0; j < 32; j++) s += y1[j] * fc2w[j * 2 + o];
        out[g * 2 + o] = s;
    }
}

// ---------------- host ----------------
extern "C" void kernel_launch(void* const* d_in, const int* in_sizes, int n_in,
                              void* d_out, int out_size) {
    (void)in_sizes; (void)n_in; (void)out_size;
    const float* x    = (const float*)d_in[0];
    const int*   ei   = (const int*)d_in[1];
    const float* ea   = (const float*)d_in[2];
    const int*   batch= (const int*)d_in[3];
    const float* W0   = (const float*)d_in[4];
    const float* as0  = (const float*)d_in[5];
    const float* ad0  = (const float*)d_in[6];
    const float* We0  = (const float*)d_in[7];
    const float* ae0  = (const float*)d_in[8];
    const float* b0   = (const float*)d_in[9];
    const float* Wh   = (const float*)d_in[10];
    const float* ash  = (const float*)d_in[11];
    const float* adh  = (const float*)d_in[12];
    const float* Weh  = (const float*)d_in[13];
    const float* aeh  = (const float*)d_in[14];
    const float* bh   = (const float*)d_in[15];
    const float* fc1w = (const float*)d_in[16];
    const float* fc1b = (const float*)d_in[17];
    const float* fc2w = (const float*)d_in[18];
    const float* fc2b = (const float*)d_in[19];
    float* out = (float*)d_out;

    const int* src = ei;
    const int* dst = ei + NE;

    void *p_cnt, *p_mean, *p_pool, *p_gcnt, *p_flag, *p_done, *p_h0, *p_h1, *p_ale;
    cudaGetSymbolAddress(&p_cnt,  d_cnt);
    cudaGetSymbolAddress(&p_mean, d_mean);
    cudaGetSymbolAddress(&p_pool, d_pool);
    cudaGetSymbolAddress(&p_gcnt, d_gcnt);
    cudaGetSymbolAddress(&p_flag, d_flagsum);
    cudaGetSymbolAddress(&p_done, d_done);
    cudaGetSymbolAddress(&p_h0,   d_h0);
    cudaGetSymbolAddress(&p_h1,   d_h1);
    cudaGetSymbolAddress(&p_ale,  d_ale);

    struct LayerCfg {
        const float* X; int fin; const float* W;
        const float* as; const float* ad; const float* b; float* hout; int relu;
    };
    LayerCfg L[3] = {
        { x,            32, W0,        as0,      ad0,      b0,      (float*)p_h0, 1 },
        { (float*)p_h0, 64, Wh,        ash,      adh,      bh,      (float*)p_h1, 0 },
        { (float*)p_h1, 64, Wh + 4096, ash + 64, adh + 64, bh + 64, (float*)p_h0, 0 },
    };

    cudaMemsetAsync(p_cnt,  0, NN * sizeof(float));
    cudaMemsetAsync(p_mean, 0, NN * 8 * sizeof(float));
    cudaMemsetAsync(p_flag, 0, SCB * sizeof(int));
    cudaMemsetAsync(p_done, 0, sizeof(int));
    cudaMemsetAsync(p_pool, 0, NGRAPH * 64 * sizeof(float));
    cudaMemsetAsync(p_gcnt, 0, NGRAPH * sizeof(float));

    // kernel launches: #4 is k_agg layer 0 (ncu capture target)
    k_countscan<<<CSB, 256>>>(dst, ea, We0, ae0, Weh, aeh);                       // 1
    k_fill1<<<(ESL + 255) / 256, 256>>>(dst);                                     // 2
    k_fill2proj<<<PB + (ESL + 255) / 256, 256>>>(src, ea,                         // 3
                                                 L[0].X, L[0].fin, L[0].W, L[0].as, L[0].ad);
    k_agg<<<NN / 2, 64>>>((const float*)p_ale,                                    // 4 <-- profiled
                          L[0].b, L[0].relu, L[0].hout, batch, 0);
    for (int l = 1; l < 3; l++) {
        k_project<<<1184, 256>>>(L[l].X, L[l].fin, L[l].W, L[l].as, L[l].ad);
        k_agg<<<NN / 2, 64>>>((const float*)p_ale + (size_t)l * ESL * 4,
                              L[l].b, L[l].relu, L[l].hout,
                              batch, (l == 2) ? 1 : 0);
    }

    k_mlp<<<1, 64>>>(fc1w, fc1b, fc2w, fc2b, out);
}

// round 16
// speedup vs baseline: 1.0682x; 1.0682x over previous
#include <cuda_runtime.h>
#include <math.h>

#define NN 100000
#define NE 1600000
#define ESL (NE + NN)
#define NGRAPH 64
#define NEG 0.2f
#define SCB 196          // scan blocks (ceil(NN/512))
#define PB  1184         // project blocks inside fused fill2+proj kernel

// ---------------- scratch (device globals; no allocation) ----------------
__device__ float    d_cnt[NN];
__device__ float    d_mean[NN * 8];
__device__ float    d_xp[NN * 64];
__device__ float    d_als[NN * 4];
__device__ float    d_ald[NN * 4];
__device__ float    d_h0[NN * 64];
__device__ float    d_h1[NN * 64];
__device__ float    d_pool[NGRAPH * 64];
__device__ float    d_gcnt[NGRAPH];
__device__ float    d_weatt[3 * 32];
// CSR
__device__ int      d_roff[NN + 1];
__device__ int      d_cur[NN];
__device__ int      d_eid[ESL];                 // CSR slot -> original edge id
__device__ int      d_csrc[ESL];                // CSR slot -> src node (coalesced write)
__device__ float    d_ale[3][(size_t)ESL * 4];  // per-layer edge logits (coalesced write)
__device__ int      d_flagsum[SCB];             // lookback: 0 = not ready, else localsum+1

// ---------------- helpers ----------------
__device__ __forceinline__ void red2(float* p, float a, float b) {
    asm volatile("red.global.add.v2.f32 [%0], {%1, %2};" :: "l"(p), "f"(a), "f"(b) : "memory");
}
__device__ __forceinline__ void red4(float* p, float a, float b, float c, float d) {
    asm volatile("red.global.add.v4.f32 [%0], {%1, %2, %3, %4};"
                 :: "l"(p), "f"(a), "f"(b), "f"(c), "f"(d) : "memory");
}

// ---------------- self-loop mean edge-attr (sum) + in-degree count ----------------
__global__ void k_count(const int* __restrict__ dst, const float* __restrict__ ea) {
    int e = blockIdx.x * blockDim.x + threadIdx.x;
    if (e >= NE) return;
    int dd = dst[e];
    atomicAdd(&d_cnt[dd], 1.0f);
    const float4* ap = (const float4*)(ea + (size_t)e * 8);
    float4 v0 = ap[0], v1 = ap[1];
    red4(&d_mean[dd * 8],     v0.x, v0.y, v0.z, v0.w);
    red4(&d_mean[dd * 8 + 4], v1.x, v1.y, v1.z, v1.w);
}

// ---------------- one-kernel scan (decoupled lookback) + weatt + roff[NN] ----------------
__global__ void k_scan(const float* __restrict__ We0, const float* __restrict__ ae0,
                       const float* __restrict__ Weh, const float* __restrict__ aeh) {
    __shared__ int sh[256];
    __shared__ int sp[256];
    int t = threadIdx.x, bid = blockIdx.x;
    int nb = bid * 512 + t * 2;
    int d0 = 0, d1 = 0;
    if (nb < NN) {                      // NN even -> nb+1 < NN too
        float2 c = *(const float2*)&d_cnt[nb];
        d0 = (int)(c.x + 0.5f) + 1;
        d1 = (int)(c.y + 0.5f) + 1;
    }
    sh[t] = d0 + d1;
    __syncthreads();
#pragma unroll
    for (int off = 1; off < 256; off <<= 1) {
        int v = (t >= off) ? sh[t - off] : 0;
        __syncthreads();
        sh[t] += v;
        __syncthreads();
    }
    int total = sh[255];
    if (t == 0) {
        __threadfence();
        atomicExch(&d_flagsum[bid], total + 1);
    }
    int pre = 0;
    if (t < bid) {
        volatile int* f = &d_flagsum[t];
        int x;
        while ((x = *f) == 0) { }
        pre = x - 1;
    }
    sp[t] = pre;
    __syncthreads();
#pragma unroll
    for (int off = 128; off; off >>= 1) {
        if (t < off) sp[t] += sp[t + off];
        __syncthreads();
    }
    int base = sp[0];
    int off0 = base + sh[t] - (d0 + d1);
    if (nb < NN) {
        d_roff[nb] = off0;          d_cur[nb] = off0;
        d_roff[nb + 1] = off0 + d0; d_cur[nb + 1] = off0 + d0;
    }
    if (bid == 0) {
        if (t < 96) {
            int l = t >> 5, r = t & 31;
            int d = r >> 2, h = r & 3;
            const float* We = (l == 0) ? We0 : (Weh + (l - 1) * 512);
            const float* ae = (l == 0) ? ae0 : (aeh + (l - 1) * 64);
            float s = 0.0f;
#pragma unroll
            for (int c = 0; c < 16; c++) s += We[d * 64 + h * 16 + c] * ae[h * 16 + c];
            d_weatt[l * 32 + d * 4 + h] = s;
        }
        if (t == 0) d_roff[NN] = ESL;
    }
}

// ---------------- fill pass 1: permutation only (one 4B scattered store per edge) ----------------
__global__ void k_fill1(const int* __restrict__ dst) {
    int e = blockIdx.x * blockDim.x + threadIdx.x;
    if (e >= ESL) return;
    int dd = (e < NE) ? dst[e] : e - NE;
    int pos = atomicAdd(&d_cur[dd], 1);
    d_eid[pos] = e;
}

// ---------------- projection body: warp handles 4 nodes x 64 cols (2 cols/lane).
// w-loads amortized across 4 nodes: 4x less smem traffic per FMA.
__device__ __forceinline__ void project_body(
        int bid, int nblocks,
        const float* __restrict__ X, int fin, const float* __restrict__ W,
        const float* __restrict__ as_, const float* __restrict__ ad_,
        float* sW, float* sx, float* sa, float* sd) {
    int tid = threadIdx.x;
    for (int i = tid; i < fin * 64; i += 256) sW[i] = W[i];
    if (tid < 64) { sa[tid] = as_[tid]; sd[tid] = ad_[tid]; }
    __syncthreads();
    int wid = tid >> 5;                 // warp handles nodes [wid*4, wid*4+4)
    int lane = tid & 31;
    int c2 = lane * 2;                  // this lane's two output cols
    int lf = (fin == 64) ? 6 : 5;
    int fmask = fin - 1;
    for (int base = bid * 32; base < NN; base += nblocks * 32) {
        for (int i = tid; i < 32 * fin; i += 256) {
            int nl = i >> lf, c = i & fmask;
            sx[nl * 64 + c] = X[(size_t)(base + nl) * fin + c];
        }
        __syncthreads();
        int n0 = base + wid * 4;
        const float* xr = sx + (size_t)(wid * 4) * 64;
        float acc[4][2] = {{0,0},{0,0},{0,0},{0,0}};
#pragma unroll 2
        for (int i = 0; i < fin; i += 4) {
            float4 x0 = *(const float4*)(xr + 0 * 64 + i);   // broadcast: 1 phase
            float4 x1 = *(const float4*)(xr + 1 * 64 + i);
            float4 x2 = *(const float4*)(xr + 2 * 64 + i);
            float4 x3 = *(const float4*)(xr + 3 * 64 + i);
            float2 w0 = *(const float2*)(sW + (i + 0) * 64 + c2);
            float2 w1 = *(const float2*)(sW + (i + 1) * 64 + c2);
            float2 w2 = *(const float2*)(sW + (i + 2) * 64 + c2);
            float2 w3 = *(const float2*)(sW + (i + 3) * 64 + c2);
            acc[0][0] += x0.x*w0.x + x0.y*w1.x + x0.z*w2.x + x0.w*w3.x;
            acc[0][1] += x0.x*w0.y + x0.y*w1.y + x0.z*w2.y + x0.w*w3.y;
            acc[1][0] += x1.x*w0.x + x1.y*w1.x + x1.z*w2.x + x1.w*w3.x;
            acc[1][1] += x1.x*w0.y + x1.y*w1.y + x1.z*w2.y + x1.w*w3.y;
            acc[2][0] += x2.x*w0.x + x2.y*w1.x + x2.z*w2.x + x2.w*w3.x;
            acc[2][1] += x2.x*w0.y + x2.y*w1.y + x2.z*w2.y + x2.w*w3.y;
            acc[3][0] += x3.x*w0.x + x3.y*w1.x + x3.z*w2.x + x3.w*w3.x;
            acc[3][1] += x3.x*w0.y + x3.y*w1.y + x3.z*w2.y + x3.w*w3.y;
        }
#pragma unroll
        for (int nl = 0; nl < 4; nl++) {
            int n = n0 + nl;
            *(float2*)(d_xp + (size_t)n * 64 + c2) = make_float2(acc[nl][0], acc[nl][1]);
            float ps = acc[nl][0] * sa[c2] + acc[nl][1] * sa[c2 + 1];
            float pd = acc[nl][0] * sd[c2] + acc[nl][1] * sd[c2 + 1];
#pragma unroll
            for (int off = 4; off; off >>= 1) {
                ps += __shfl_xor_sync(0xffffffffu, ps, off);
                pd += __shfl_xor_sync(0xffffffffu, pd, off);
            }
            if ((lane & 7) == 0) {
                int h = lane >> 3;
                d_als[n * 4 + h] = ps;
                d_ald[n * 4 + h] = pd;
            }
        }
        __syncthreads();
    }
}

// ---------------- fill pass 2: thread = CSR slot; gather-compute, coalesced writes ----------------
__device__ __forceinline__ void fill2_body(int slot, const int* __restrict__ src,
                                           const float* __restrict__ ea, const float* sw) {
    int e = d_eid[slot];                 // coalesced
    int s;
    float a[8];
    if (e < NE) {
        s = src[e];                      // scattered 4B read (clean sector fetch)
        const float4* ap = (const float4*)(ea + (size_t)e * 8);  // scattered 32B read
        float4 v0 = ap[0], v1 = ap[1];
        a[0] = v0.x; a[1] = v0.y; a[2] = v0.z; a[3] = v0.w;
        a[4] = v1.x; a[5] = v1.y; a[6] = v1.z; a[7] = v1.w;
    } else {
        int n = e - NE;
        s = n;
        const float4* ap = (const float4*)(d_mean + (size_t)n * 8);
        float4 v0 = ap[0], v1 = ap[1];
        float ic = 1.0f / fmaxf(d_cnt[n], 1.0f);
        a[0] = v0.x * ic; a[1] = v0.y * ic; a[2] = v0.z * ic; a[3] = v0.w * ic;
        a[4] = v1.x * ic; a[5] = v1.y * ic; a[6] = v1.z * ic; a[7] = v1.w * ic;
    }
    d_csrc[slot] = s;                    // coalesced
#pragma unroll
    for (int l = 0; l < 3; l++) {
        float4 o;
        float* po = (float*)&o;
#pragma unroll
        for (int h = 0; h < 4; h++) {
            float sum = 0.0f;
#pragma unroll
            for (int d = 0; d < 8; d++) sum += a[d] * sw[l * 32 + d * 4 + h];
            po[h] = sum;
        }
        *(float4*)(&d_ale[l][(size_t)slot * 4]) = o;   // coalesced 16B
    }
}

// ---------------- fused: fill2 (blocks >= PB) + project layer0 (blocks < PB) ----------------
__global__ void k_fill2proj(const int* __restrict__ src, const float* __restrict__ ea,
                            const float* __restrict__ X, int fin, const float* __restrict__ W,
                            const float* __restrict__ as_, const float* __restrict__ ad_) {
    __shared__ float sW[64 * 64];
    __shared__ float sx[32 * 64];
    __shared__ float sa[64], sd[64];
    __shared__ float sw[96];
    if (blockIdx.x < PB) {
        project_body(blockIdx.x, PB, X, fin, W, as_, ad_, sW, sx, sa, sd);
        return;
    }
    if (threadIdx.x < 96) sw[threadIdx.x] = d_weatt[threadIdx.x];
    __syncthreads();
    int slot = (blockIdx.x - PB) * 256 + threadIdx.x;
    if (slot >= ESL) return;
    fill2_body(slot, src, ea, sw);
}

// ---------------- standalone projection (layers 1,2) ----------------
__global__ void k_project(const float* __restrict__ X, int fin, const float* __restrict__ W,
                          const float* __restrict__ as_, const float* __restrict__ ad_) {
    __shared__ float sW[64 * 64];
    __shared__ float sx[32 * 64];
    __shared__ float sa[64], sd[64];
    project_body(blockIdx.x, gridDim.x, X, fin, W, as_, ad_, sW, sx, sa, sd);
}

// ---------------- fused single-pass softmax-aggregate
// producer: lane = h*8+sub computes coef for (edge sub, head h), distance-1 pipelined.
// consumer: 2 xp rows per j-step; lane covers cols (lane&15)*4 of row-group lane>>4.
// epilogue: shfl-xor-16 combine; lanes 0-15 write float4.
__global__ void __launch_bounds__(64)
k_agg(const float* __restrict__ ale, const float* __restrict__ b,
      int dorelu, float* __restrict__ out,
      const int* __restrict__ batch, int dopool) {
    int tid = threadIdx.x;
    int warp = (blockIdx.x * 64 + tid) >> 5;
    if (warp >= NN) return;
    int lane = tid & 31;
    int h = lane >> 3, sub = lane & 7;   // producer role
    int r = lane >> 4;                   // consumer row-group (edge parity)
    int q = lane & 15;                   // consumer col quad: cols [q*4, q*4+4)
    int hq = q >> 2;                     // head of those cols
    int beg = d_roff[warp];
    int end = d_roff[warp + 1];
    float ald_h = d_ald[warp * 4 + h];

    // pipeline prologue
    int myp = beg + sub;
    int s = 0;
    float av = -INFINITY;                // invalid lanes: alpha = -inf -> exp = 0
    if (myp < end) {
        s = d_csrc[myp];
        av = ale[(size_t)myp * 4 + h];
    }
    float alsv = d_als[s * 4 + h];

    float den = 0.0f, a0 = 0.0f, a1 = 0.0f, a2 = 0.0f, a3 = 0.0f;
    for (int p0 = beg; p0 < end; p0 += 8) {
        float a = alsv + ald_h + av;
        float al = a > 0.0f ? a : NEG * a;
        float c = __expf(al);
        int scur = s;
        int myp2 = p0 + 8 + sub;
        s = 0; av = -INFINITY;
        if (myp2 < end) {
            s = d_csrc[myp2];
            av = ale[(size_t)myp2 * 4 + h];
        }
        alsv = d_als[s * 4 + h];
#pragma unroll
        for (int j = 0; j < 4; j++) {
            int eidx = 2 * j + r;
            float cj = __shfl_sync(0xffffffffu, c, hq * 8 + eidx);
            int   sj = __shfl_sync(0xffffffffu, scur, eidx);
            float4 v = *(const float4*)(d_xp + (size_t)sj * 64 + q * 4);
            den += cj; a0 += cj * v.x; a1 += cj * v.y; a2 += cj * v.z; a3 += cj * v.w;
        }
    }
    // combine the two row-groups (lanes L and L+16 cover identical cols)
    den += __shfl_xor_sync(0xffffffffu, den, 16);
    a0  += __shfl_xor_sync(0xffffffffu, a0, 16);
    a1  += __shfl_xor_sync(0xffffffffu, a1, 16);
    a2  += __shfl_xor_sync(0xffffffffu, a2, 16);
    a3  += __shfl_xor_sync(0xffffffffu, a3, 16);
    if (lane < 16) {
        float inv = 1.0f / (den + 1e-16f);
        float4 bb = *(const float4*)(b + q * 4);
        float o0 = a0 * inv + bb.x;
        float o1 = a1 * inv + bb.y;
        float o2 = a2 * inv + bb.z;
        float o3 = a3 * inv + bb.w;
        if (dorelu) {
            o0 = fmaxf(o0, 0.0f); o1 = fmaxf(o1, 0.0f);
            o2 = fmaxf(o2, 0.0f); o3 = fmaxf(o3, 0.0f);
        }
        if (dopool) {
            int g = batch[warp];
            red2(&d_pool[g * 64 + q * 4], o0, o1);
            red2(&d_pool[g * 64 + q * 4 + 2], o2, o3);
            if (q == 0) atomicAdd(&d_gcnt[g], 1.0f);
        } else {
            *(float4*)(out + (size_t)warp * 64 + q * 4) = make_float4(o0, o1, o2, o3);
        }
    }
}

// ---------------- MLP head ----------------
__global__ void k_mlp(const float* __restrict__ fc1w, const float* __restrict__ fc1b,
                      const float* __restrict__ fc2w, const float* __restrict__ fc2b,
                      float* __restrict__ out) {
    int g = threadIdx.x;
    if (g >= NGRAPH) return;
    float ic = 1.0f / fmaxf(d_gcnt[g], 1.0f);
    float hr[64];
#pragma unroll
    for (int c = 0; c < 64; c++) hr[c] = d_pool[g * 64 + c] * ic;
    float y1[32];
#pragma unroll
    for (int j = 0; j < 32; j++) {
        float s = fc1b[j];
#pragma unroll
        for (int c = 0; c < 64; c++) s += hr[c] * fc1w[c * 32 + j];
        y1[j] = fmaxf(s, 0.0f);
    }
#pragma unroll
    for (int o = 0; o < 2; o++) {
        float s = fc2b[o];
#pragma unroll
        for (int j = 0; j < 32; j++) s += y1[j] * fc2w[j * 2 + o];
        out[g * 2 + o] = s;
    }
}

// ---------------- host ----------------
extern "C" void kernel_launch(void* const* d_in, const int* in_sizes, int n_in,
                              void* d_out, int out_size) {
    (void)in_sizes; (void)n_in; (void)out_size;
    const float* x    = (const float*)d_in[0];
    const int*   ei   = (const int*)d_in[1];
    const float* ea   = (const float*)d_in[2];
    const int*   batch= (const int*)d_in[3];
    const float* W0   = (const float*)d_in[4];
    const float* as0  = (const float*)d_in[5];
    const float* ad0  = (const float*)d_in[6];
    const float* We0  = (const float*)d_in[7];
    const float* ae0  = (const float*)d_in[8];
    const float* b0   = (const float*)d_in[9];
    const float* Wh   = (const float*)d_in[10];
    const float* ash  = (const float*)d_in[11];
    const float* adh  = (const float*)d_in[12];
    const float* Weh  = (const float*)d_in[13];
    const float* aeh  = (const float*)d_in[14];
    const float* bh   = (const float*)d_in[15];
    const float* fc1w = (const float*)d_in[16];
    const float* fc1b = (const float*)d_in[17];
    const float* fc2w = (const float*)d_in[18];
    const float* fc2b = (const float*)d_in[19];
    float* out = (float*)d_out;

    const int* src = ei;
    const int* dst = ei + NE;

    void *p_cnt, *p_mean, *p_pool, *p_gcnt, *p_flag, *p_h0, *p_h1, *p_ale;
    cudaGetSymbolAddress(&p_cnt,  d_cnt);
    cudaGetSymbolAddress(&p_mean, d_mean);
    cudaGetSymbolAddress(&p_pool, d_pool);
    cudaGetSymbolAddress(&p_gcnt, d_gcnt);
    cudaGetSymbolAddress(&p_flag, d_flagsum);
    cudaGetSymbolAddress(&p_h0,   d_h0);
    cudaGetSymbolAddress(&p_h1,   d_h1);
    cudaGetSymbolAddress(&p_ale,  d_ale);

    struct LayerCfg {
        const float* X; int fin; const float* W;
        const float* as; const float* ad; const float* b; float* hout; int relu;
    };
    LayerCfg L[3] = {
        { x,            32, W0,        as0,      ad0,      b0,      (float*)p_h0, 1 },
        { (float*)p_h0, 64, Wh,        ash,      adh,      bh,      (float*)p_h1, 0 },
        { (float*)p_h1, 64, Wh + 4096, ash + 64, adh + 64, bh + 64, (float*)p_h0, 0 },
    };

    cudaMemsetAsync(p_cnt,  0, NN * sizeof(float));
    cudaMemsetAsync(p_mean, 0, NN * 8 * sizeof(float));
    cudaMemsetAsync(p_flag, 0, SCB * sizeof(int));
    cudaMemsetAsync(p_pool, 0, NGRAPH * 64 * sizeof(float));
    cudaMemsetAsync(p_gcnt, 0, NGRAPH * sizeof(float));

    // kernel launches: #4 is the fused fill2+proj0 (ncu capture target)
    k_count<<<(NE + 255) / 256, 256>>>(dst, ea);                                  // 1
    k_scan<<<SCB, 256>>>(We0, ae0, Weh, aeh);                                     // 2
    k_fill1<<<(ESL + 255) / 256, 256>>>(dst);                                     // 3
    k_fill2proj<<<PB + (ESL + 255) / 256, 256>>>(src, ea,                         // 4 <-- profiled
                                                 L[0].X, L[0].fin, L[0].W, L[0].as, L[0].ad);
    k_agg<<<NN / 2, 64>>>((const float*)p_ale,                                    // 5
                          L[0].b, L[0].relu, L[0].hout, batch, 0);
    for (int l = 1; l < 3; l++) {
        k_project<<<1184, 256>>>(L[l].X, L[l].fin, L[l].W, L[l].as, L[l].ad);
        k_agg<<<NN / 2, 64>>>((const float*)p_ale + (size_t)l * ESL * 4,
                              L[l].b, L[l].relu, L[l].hout,
                              batch, (l == 2) ? 1 : 0);
    }

    k_mlp<<<1, 64>>>(fc1w, fc1b, fc2w, fc2b, out);
}

// round 17
// speedup vs baseline: 1.3112x; 1.2275x over previous
#include <cuda_runtime.h>
#include <math.h>

#define NN 100000
#define NE 1600000
#define ESL (NE + NN)
#define NGRAPH 64
#define NEG 0.2f
#define SCB 196          // scan blocks (ceil(NN/512))
#define PB  1184         // project blocks inside fused fill2+proj kernel

// ---------------- scratch (device globals; no allocation) ----------------
__device__ float    d_cnt[NN];
__device__ float    d_mean[NN * 8];
__device__ float    d_xp[NN * 64];
__device__ float    d_als[NN * 4];
__device__ float    d_ald[NN * 4];
__device__ float    d_h0[NN * 64];
__device__ float    d_h1[NN * 64];
__device__ float    d_pool[NGRAPH * 64];
__device__ float    d_gcnt[NGRAPH];
__device__ float    d_weatt[3 * 32];
// CSR
__device__ int      d_roff[NN + 1];
__device__ int      d_cur[NN];
__device__ int      d_eid[ESL];                 // CSR slot -> original edge id
__device__ int      d_csrc[ESL];                // CSR slot -> src node (coalesced write)
__device__ float    d_ale[3][(size_t)ESL * 4];  // per-layer edge logits (coalesced write)
__device__ int      d_flagsum[SCB];             // lookback: 0 = not ready, else localsum+1

// ---------------- helpers ----------------
__device__ __forceinline__ void red2(float* p, float a, float b) {
    asm volatile("red.global.add.v2.f32 [%0], {%1, %2};" :: "l"(p), "f"(a), "f"(b) : "memory");
}

// ---------------- self-loop mean edge-attr (sum) + in-degree count ----------------
__global__ void k_count(const int* __restrict__ dst, const float* __restrict__ ea) {
    int e = blockIdx.x * blockDim.x + threadIdx.x;
    if (e >= NE) return;
    int dd = dst[e];
    atomicAdd(&d_cnt[dd], 1.0f);
#pragma unroll
    for (int d = 0; d < 8; d += 2)
        red2(&d_mean[dd * 8 + d], ea[(size_t)e * 8 + d], ea[(size_t)e * 8 + d + 1]);
}

// ---------------- one-kernel scan (decoupled lookback) + weatt + roff[NN] ----------------
__global__ void k_scan(const float* __restrict__ We0, const float* __restrict__ ae0,
                       const float* __restrict__ Weh, const float* __restrict__ aeh) {
    __shared__ int sh[256];
    __shared__ int sp[256];
    int t = threadIdx.x, bid = blockIdx.x;
    int nb = bid * 512 + t * 2;
    int d0 = 0, d1 = 0;
    if (nb < NN) {                      // NN even -> nb+1 < NN too
        float2 c = *(const float2*)&d_cnt[nb];
        d0 = (int)(c.x + 0.5f) + 1;
        d1 = (int)(c.y + 0.5f) + 1;
    }
    sh[t] = d0 + d1;
    __syncthreads();
#pragma unroll
    for (int off = 1; off < 256; off <<= 1) {
        int v = (t >= off) ? sh[t - off] : 0;
        __syncthreads();
        sh[t] += v;
        __syncthreads();
    }
    int total = sh[255];
    if (t == 0) {
        __threadfence();
        atomicExch(&d_flagsum[bid], total + 1);
    }
    int pre = 0;
    if (t < bid) {
        volatile int* f = &d_flagsum[t];
        int x;
        while ((x = *f) == 0) { }
        pre = x - 1;
    }
    sp[t] = pre;
    __syncthreads();
#pragma unroll
    for (int off = 128; off; off >>= 1) {
        if (t < off) sp[t] += sp[t + off];
        __syncthreads();
    }
    int base = sp[0];
    int off0 = base + sh[t] - (d0 + d1);
    if (nb < NN) {
        d_roff[nb] = off0;          d_cur[nb] = off0;
        d_roff[nb + 1] = off0 + d0; d_cur[nb + 1] = off0 + d0;
    }
    if (bid == 0) {
        if (t < 96) {
            int l = t >> 5, r = t & 31;
            int d = r >> 2, h = r & 3;
            const float* We = (l == 0) ? We0 : (Weh + (l - 1) * 512);
            const float* ae = (l == 0) ? ae0 : (aeh + (l - 1) * 64);
            float s = 0.0f;
#pragma unroll
            for (int c = 0; c < 16; c++) s += We[d * 64 + h * 16 + c] * ae[h * 16 + c];
            d_weatt[l * 32 + d * 4 + h] = s;
        }
        if (t == 0) d_roff[NN] = ESL;
    }
}

// ---------------- fill pass 1: permutation only (one 4B scattered store per edge) ----------------
__global__ void k_fill1(const int* __restrict__ dst) {
    int e = blockIdx.x * blockDim.x + threadIdx.x;
    if (e >= ESL) return;
    int dd = (e < NE) ? dst[e] : e - NE;
    int pos = atomicAdd(&d_cur[dd], 1);
    d_eid[pos] = e;
}

// ---------------- projection body: warp handles 4 nodes x 64 cols (2 cols/lane).
// w-loads amortized across 4 nodes: 4x less smem traffic per FMA.
__device__ __forceinline__ void project_body(
        int bid, int nblocks,
        const float* __restrict__ X, int fin, const float* __restrict__ W,
        const float* __restrict__ as_, const float* __restrict__ ad_,
        float* sW, float* sx, float* sa, float* sd) {
    int tid = threadIdx.x;
    for (int i = tid; i < fin * 64; i += 256) sW[i] = W[i];
    if (tid < 64) { sa[tid] = as_[tid]; sd[tid] = ad_[tid]; }
    __syncthreads();
    int wid = tid >> 5;                 // warp handles nodes [wid*4, wid*4+4)
    int lane = tid & 31;
    int c2 = lane * 2;                  // this lane's two output cols
    int lf = (fin == 64) ? 6 : 5;
    int fmask = fin - 1;
    for (int base = bid * 32; base < NN; base += nblocks * 32) {
        for (int i = tid; i < 32 * fin; i += 256) {
            int nl = i >> lf, c = i & fmask;
            sx[nl * 64 + c] = X[(size_t)(base + nl) * fin + c];
        }
        __syncthreads();
        int n0 = base + wid * 4;
        const float* xr = sx + (size_t)(wid * 4) * 64;
        float acc[4][2] = {{0,0},{0,0},{0,0},{0,0}};
#pragma unroll 2
        for (int i = 0; i < fin; i += 4) {
            float4 x0 = *(const float4*)(xr + 0 * 64 + i);   // broadcast: 1 phase
            float4 x1 = *(const float4*)(xr + 1 * 64 + i);
            float4 x2 = *(const float4*)(xr + 2 * 64 + i);
            float4 x3 = *(const float4*)(xr + 3 * 64 + i);
            float2 w0 = *(const float2*)(sW + (i + 0) * 64 + c2);
            float2 w1 = *(const float2*)(sW + (i + 1) * 64 + c2);
            float2 w2 = *(const float2*)(sW + (i + 2) * 64 + c2);
            float2 w3 = *(const float2*)(sW + (i + 3) * 64 + c2);
            acc[0][0] += x0.x*w0.x + x0.y*w1.x + x0.z*w2.x + x0.w*w3.x;
            acc[0][1] += x0.x*w0.y + x0.y*w1.y + x0.z*w2.y + x0.w*w3.y;
            acc[1][0] += x1.x*w0.x + x1.y*w1.x + x1.z*w2.x + x1.w*w3.x;
            acc[1][1] += x1.x*w0.y + x1.y*w1.y + x1.z*w2.y + x1.w*w3.y;
            acc[2][0] += x2.x*w0.x + x2.y*w1.x + x2.z*w2.x + x2.w*w3.x;
            acc[2][1] += x2.x*w0.y + x2.y*w1.y + x2.z*w2.y + x2.w*w3.y;
            acc[3][0] += x3.x*w0.x + x3.y*w1.x + x3.z*w2.x + x3.w*w3.x;
            acc[3][1] += x3.x*w0.y + x3.y*w1.y + x3.z*w2.y + x3.w*w3.y;
        }
#pragma unroll
        for (int nl = 0; nl < 4; nl++) {
            int n = n0 + nl;
            *(float2*)(d_xp + (size_t)n * 64 + c2) = make_float2(acc[nl][0], acc[nl][1]);
            float ps = acc[nl][0] * sa[c2] + acc[nl][1] * sa[c2 + 1];
            float pd = acc[nl][0] * sd[c2] + acc[nl][1] * sd[c2 + 1];
#pragma unroll
            for (int off = 4; off; off >>= 1) {
                ps += __shfl_xor_sync(0xffffffffu, ps, off);
                pd += __shfl_xor_sync(0xffffffffu, pd, off);
            }
            if ((lane & 7) == 0) {
                int h = lane >> 3;
                d_als[n * 4 + h] = ps;
                d_ald[n * 4 + h] = pd;
            }
        }
        __syncthreads();
    }
}

// ---------------- fill pass 2: thread = CSR slot; gather-compute, coalesced writes ----------------
__device__ __forceinline__ void fill2_body(int slot, const int* __restrict__ src,
                                           const float* __restrict__ ea, const float* sw) {
    int e = d_eid[slot];                 // coalesced
    int s;
    float a[8];
    if (e < NE) {
        s = src[e];                      // scattered 4B read (clean sector fetch)
        const float4* ap = (const float4*)(ea + (size_t)e * 8);  // scattered 32B read
        float4 v0 = ap[0], v1 = ap[1];
        a[0] = v0.x; a[1] = v0.y; a[2] = v0.z; a[3] = v0.w;
        a[4] = v1.x; a[5] = v1.y; a[6] = v1.z; a[7] = v1.w;
    } else {
        int n = e - NE;
        s = n;
        const float4* ap = (const float4*)(d_mean + (size_t)n * 8);
        float4 v0 = ap[0], v1 = ap[1];
        float ic = 1.0f / fmaxf(d_cnt[n], 1.0f);
        a[0] = v0.x * ic; a[1] = v0.y * ic; a[2] = v0.z * ic; a[3] = v0.w * ic;
        a[4] = v1.x * ic; a[5] = v1.y * ic; a[6] = v1.z * ic; a[7] = v1.w * ic;
    }
    d_csrc[slot] = s;                    // coalesced
#pragma unroll
    for (int l = 0; l < 3; l++) {
        float4 o;
        float* po = (float*)&o;
#pragma unroll
        for (int h = 0; h < 4; h++) {
            float sum = 0.0f;
#pragma unroll
            for (int d = 0; d < 8; d++) sum += a[d] * sw[l * 32 + d * 4 + h];
            po[h] = sum;
        }
        *(float4*)(&d_ale[l][(size_t)slot * 4]) = o;   // coalesced 16B
    }
}

// ---------------- fused: fill2 (blocks >= PB) + project layer0 (blocks < PB) ----------------
__global__ void k_fill2proj(const int* __restrict__ src, const float* __restrict__ ea,
                            const float* __restrict__ X, int fin, const float* __restrict__ W,
                            const float* __restrict__ as_, const float* __restrict__ ad_) {
    __shared__ float sW[64 * 64];
    __shared__ float sx[32 * 64];
    __shared__ float sa[64], sd[64];
    __shared__ float sw[96];
    if (blockIdx.x < PB) {
        project_body(blockIdx.x, PB, X, fin, W, as_, ad_, sW, sx, sa, sd);
        return;
    }
    if (threadIdx.x < 96) sw[threadIdx.x] = d_weatt[threadIdx.x];
    __syncthreads();
    int slot = (blockIdx.x - PB) * 256 + threadIdx.x;
    if (slot >= ESL) return;
    fill2_body(slot, src, ea, sw);
}

// ---------------- standalone projection (layers 1,2): one 32-node tile per block ----------------
__global__ void k_project(const float* __restrict__ X, int fin, const float* __restrict__ W,
                          const float* __restrict__ as_, const float* __restrict__ ad_) {
    __shared__ float sW[64 * 64];
    __shared__ float sx[32 * 64];
    __shared__ float sa[64], sd[64];
    project_body(blockIdx.x, gridDim.x, X, fin, W, as_, ad_, sW, sx, sa, sd);
}

// ---------------- fused single-pass softmax-aggregate, distance-1 software pipeline
// warp per dst node; 64-thread blocks (2 warps) minimize block-tail waste.
// dopool: last layer skips the global h store and reduces straight into the pool.
__global__ void __launch_bounds__(64)
k_agg(const float* __restrict__ ale, const float* __restrict__ b,
      int dorelu, float* __restrict__ out,
      const int* __restrict__ batch, int dopool) {
    int tid = threadIdx.x;
    int warp = (blockIdx.x * 64 + tid) >> 5;
    if (warp >= NN) return;
    int lane = tid & 31;
    int h = lane >> 3, sub = lane & 7;
    int beg = d_roff[warp];
    int end = d_roff[warp + 1];
    float ald_h = d_ald[warp * 4 + h];
    float b0 = b[lane * 2], b1 = b[lane * 2 + 1];

    // pipeline prologue: load batch 0's (s, ale, als)
    int myp = beg + sub;
    int s = 0;
    float av = -INFINITY;                // invalid lanes: alpha = -inf -> exp = 0
    if (myp < end) {
        s = d_csrc[myp];
        av = ale[(size_t)myp * 4 + h];
    }
    float alsv = d_als[s * 4 + h];

    float den = 0.0f, a0 = 0.0f, a1 = 0.0f;
    for (int p0 = beg; p0 < end; p0 += 8) {
        float a = alsv + ald_h + av;     // -inf propagates for invalid lanes
        float al = a > 0.0f ? a : NEG * a;
        float c = __expf(al);
        int scur = s;
        int myp2 = p0 + 8 + sub;
        s = 0; av = -INFINITY;
        if (myp2 < end) {
            s = d_csrc[myp2];
            av = ale[(size_t)myp2 * 4 + h];
        }
        alsv = d_als[s * 4 + h];
#pragma unroll
        for (int j = 0; j < 8; j++) {
            float cj = __shfl_sync(0xffffffffu, c, h * 8 + j);
            int   sj = __shfl_sync(0xffffffffu, scur, j);
            float2 v = *(const float2*)(d_xp + (size_t)sj * 64 + lane * 2);
            den += cj; a0 += cj * v.x; a1 += cj * v.y;
        }
    }
    float inv = 1.0f / (den + 1e-16f);
    float o0 = a0 * inv + b0;
    float o1 = a1 * inv + b1;
    if (dorelu) { o0 = fmaxf(o0, 0.0f); o1 = fmaxf(o1, 0.0f); }
    if (dopool) {
        int g = batch[warp];
        red2(&d_pool[g * 64 + lane * 2], o0, o1);
        if (lane == 0) atomicAdd(&d_gcnt[g], 1.0f);
    } else {
        *(float2*)(out + (size_t)warp * 64 + lane * 2) = make_float2(o0, o1);
    }
}

// ---------------- MLP head ----------------
__global__ void k_mlp(const float* __restrict__ fc1w, const float* __restrict__ fc1b,
                      const float* __restrict__ fc2w, const float* __restrict__ fc2b,
                      float* __restrict__ out) {
    int g = threadIdx.x;
    if (g >= NGRAPH) return;
    float ic = 1.0f / fmaxf(d_gcnt[g], 1.0f);
    float hr[64];
#pragma unroll
    for (int c = 0; c < 64; c++) hr[c] = d_pool[g * 64 + c] * ic;
    float y1[32];
#pragma unroll
    for (int j = 0; j < 32; j++) {
        float s = fc1b[j];
#pragma unroll
        for (int c = 0; c < 64; c++) s += hr[c] * fc1w[c * 32 + j];
        y1[j] = fmaxf(s, 0.0f);
    }
#pragma unroll
    for (int o = 0; o < 2; o++) {
        float s = fc2b[o];
#pragma unroll
        for (int j = 0; j < 32; j++) s += y1[j] * fc2w[j * 2 + o];
        out[g * 2 + o] = s;
    }
}

// ---------------- host ----------------
extern "C" void kernel_launch(void* const* d_in, const int* in_sizes, int n_in,
                              void* d_out, int out_size) {
    (void)in_sizes; (void)n_in; (void)out_size;
    const float* x    = (const float*)d_in[0];
    const int*   ei   = (const int*)d_in[1];
    const float* ea   = (const float*)d_in[2];
    const int*   batch= (const int*)d_in[3];
    const float* W0   = (const float*)d_in[4];
    const float* as0  = (const float*)d_in[5];
    const float* ad0  = (const float*)d_in[6];
    const float* We0  = (const float*)d_in[7];
    const float* ae0  = (const float*)d_in[8];
    const float* b0   = (const float*)d_in[9];
    const float* Wh   = (const float*)d_in[10];
    const float* ash  = (const float*)d_in[11];
    const float* adh  = (const float*)d_in[12];
    const float* Weh  = (const float*)d_in[13];
    const float* aeh  = (const float*)d_in[14];
    const float* bh   = (const float*)d_in[15];
    const float* fc1w = (const float*)d_in[16];
    const float* fc1b = (const float*)d_in[17];
    const float* fc2w = (const float*)d_in[18];
    const float* fc2b = (const float*)d_in[19];
    float* out = (float*)d_out;

    const int* src = ei;
    const int* dst = ei + NE;

    void *p_cnt, *p_mean, *p_pool, *p_gcnt, *p_flag, *p_h0, *p_h1, *p_ale;
    cudaGetSymbolAddress(&p_cnt,  d_cnt);
    cudaGetSymbolAddress(&p_mean, d_mean);
    cudaGetSymbolAddress(&p_pool, d_pool);
    cudaGetSymbolAddress(&p_gcnt, d_gcnt);
    cudaGetSymbolAddress(&p_flag, d_flagsum);
    cudaGetSymbolAddress(&p_h0,   d_h0);
    cudaGetSymbolAddress(&p_h1,   d_h1);
    cudaGetSymbolAddress(&p_ale,  d_ale);

    struct LayerCfg {
        const float* X; int fin; const float* W;
        const float* as; const float* ad; const float* b; float* hout; int relu;
    };
    LayerCfg L[3] = {
        { x,            32, W0,        as0,      ad0,      b0,      (float*)p_h0, 1 },
        { (float*)p_h0, 64, Wh,        ash,      adh,      bh,      (float*)p_h1, 0 },
        { (float*)p_h1, 64, Wh + 4096, ash + 64, adh + 64, bh + 64, (float*)p_h0, 0 },
    };

    cudaMemsetAsync(p_cnt,  0, NN * sizeof(float));
    cudaMemsetAsync(p_mean, 0, NN * 8 * sizeof(float));
    cudaMemsetAsync(p_flag, 0, SCB * sizeof(int));
    cudaMemsetAsync(p_pool, 0, NGRAPH * 64 * sizeof(float));
    cudaMemsetAsync(p_gcnt, 0, NGRAPH * sizeof(float));

    // kernel launches: #4 is the fused fill2+proj0 (ncu capture target)
    k_count<<<(NE + 255) / 256, 256>>>(dst, ea);                                  // 1
    k_scan<<<SCB, 256>>>(We0, ae0, Weh, aeh);                                     // 2
    k_fill1<<<(ESL + 255) / 256, 256>>>(dst);                                     // 3
    k_fill2proj<<<PB + (ESL + 255) / 256, 256>>>(src, ea,                         // 4 <-- profiled
                                                 L[0].X, L[0].fin, L[0].W, L[0].as, L[0].ad);
    k_agg<<<NN / 2, 64>>>((const float*)p_ale,                                    // 5
                          L[0].b, L[0].relu, L[0].hout, batch, 0);
    for (int l = 1; l < 3; l++) {
        k_project<<<(NN + 31) / 32, 256>>>(L[l].X, L[l].fin, L[l].W, L[l].as, L[l].ad);
        k_agg<<<NN / 2, 64>>>((const float*)p_ale + (size_t)l * ESL * 4,
                              L[l].b, L[l].relu, L[l].hout,
                              batch, (l == 2) ? 1 : 0);
    }

    k_mlp<<<1, 64>>>(fc1w, fc1b, fc2w, fc2b, out);
}